// round 11
// baseline (speedup 1.0000x reference)
#include <cuda_runtime.h>
#include <cuda_pipeline.h>

// Mat2Twist: rotation matrix (3x3) -> axis-angle (3). Memory-bound.
//
// R11: 4-stage cp.async pipeline over 128-matrix tiles (persistent grid).
//   - same 24.6KB smem footprint as R8 (8 CTAs/SM) but 3 tiles in flight:
//     compute+store of tile k fully overlapped by loads of k+1..k+3
//   - smaller per-commit load batch (~1.1 float4/thread) smooths LSU issue
//     (R5 lesson: big front-batched LDG groups cause cross-CTA queue spread)
//   - __stcs streaming stores (touch-once output)

#define TPB   256
#define MATS  128
#define F4T   ((MATS * 9) / 4)   // 288 float4 per tile
#define NSTG  4

__global__ __launch_bounds__(TPB) void mat2twist_kernel(
    const float* __restrict__ in, float* __restrict__ out,
    int n, int nFullTiles)
{
    __shared__ float4 s_in[NSTG][F4T];          // 4 * 4608 B
    __shared__ float  s_out[NSTG][MATS * 3];    // 4 * 1536 B

    const int tid = threadIdx.x;
    const float4* __restrict__ gin4 = reinterpret_cast<const float4*>(in);

    // ---- prologue: prefetch up to 3 tiles, one commit group each ----
    #pragma unroll
    for (int p = 0; p < NSTG - 1; p++) {
        int t = blockIdx.x + p * gridDim.x;
        if (t < nFullTiles) {
            const float4* src = gin4 + (size_t)t * F4T;
            __pipeline_memcpy_async(&s_in[p][tid], src + tid, 16);
            if (tid < F4T - TPB)
                __pipeline_memcpy_async(&s_in[p][tid + TPB], src + tid + TPB, 16);
        }
        __pipeline_commit();
    }

    int k = 0;
    for (int tile = blockIdx.x; tile < nFullTiles; tile += gridDim.x, k++) {
        const int buf = k & (NSTG - 1);

        // ---- prefetch tile k+3 into slot (k+3)%4 (== slot read in k-1,
        //      whose reads were ordered by the previous post-compute barrier)
        int nxt = tile + (NSTG - 1) * gridDim.x;
        if (nxt < nFullTiles) {
            const int nb = (k + NSTG - 1) & (NSTG - 1);
            const float4* src = gin4 + (size_t)nxt * F4T;
            __pipeline_memcpy_async(&s_in[nb][tid], src + tid, 16);
            if (tid < F4T - TPB)
                __pipeline_memcpy_async(&s_in[nb][tid + TPB], src + tid + TPB, 16);
        }
        __pipeline_commit();
        __pipeline_wait_prior(NSTG - 1);   // current tile's group complete
        __syncthreads();

        // ---- compute current tile (each thread < MATS handles one matrix;
        //      MATS=128 < TPB=256: two threads share? No — threads 128..255
        //      handle nothing for compute; instead split: thread t computes
        //      matrix t/2's half? Simpler: threads 0..127 compute. To keep
        //      all lanes busy, map 2 threads per matrix is overkill; compute
        //      is cheap, so let lower half do it. ----
        if (tid < MATS) {
            const float* m = reinterpret_cast<const float*>(s_in[buf]) + tid * 9;
            float m00 = m[0], m01 = m[1], m02 = m[2];
            float m10 = m[3], m11 = m[4], m12 = m[5];
            float m20 = m[6], m21 = m[7], m22 = m[8];

            float c = 0.5f * (m00 + m11 + m22 - 1.0f);
            c = fminf(1.0f, fmaxf(-1.0f, c));
            // sin(acos(c)) = sqrt(1-c^2); theta in [0.1, pi-0.1] keeps it safe
            float scale = 0.5f * acosf(c) * rsqrtf(fmaxf(1.0f - c * c, 1e-12f));

            s_out[buf][tid * 3 + 0] = scale * (m21 - m12);
            s_out[buf][tid * 3 + 1] = scale * (m02 - m20);
            s_out[buf][tid * 3 + 2] = scale * (m10 - m01);
        }
        __syncthreads();

        // ---- coalesced store: 96 float4 ----
        float4* __restrict__ gout =
            reinterpret_cast<float4*>(out + (size_t)tile * MATS * 3);
        const float4* so4 = reinterpret_cast<const float4*>(s_out[buf]);
        if (tid < (MATS * 3) / 4)
            __stcs(gout + tid, so4[tid]);
    }

    // ---- tail: matrices beyond the last full tile (scalar) ----
    int tailStart = nFullTiles * MATS;
    for (int i = tailStart + blockIdx.x * TPB + tid; i < n;
         i += gridDim.x * TPB) {
        const float* m = in + (size_t)i * 9;
        float m00 = m[0], m01 = m[1], m02 = m[2];
        float m10 = m[3], m11 = m[4], m12 = m[5];
        float m20 = m[6], m21 = m[7], m22 = m[8];

        float c = 0.5f * (m00 + m11 + m22 - 1.0f);
        c = fminf(1.0f, fmaxf(-1.0f, c));
        float scale = 0.5f * acosf(c) * rsqrtf(fmaxf(1.0f - c * c, 1e-12f));

        out[(size_t)i * 3 + 0] = scale * (m21 - m12);
        out[(size_t)i * 3 + 1] = scale * (m02 - m20);
        out[(size_t)i * 3 + 2] = scale * (m10 - m01);
    }
}

extern "C" void kernel_launch(void* const* d_in, const int* in_sizes, int n_in,
                              void* d_out, int out_size)
{
    const float* in = (const float*)d_in[0];
    float* out = (float*)d_out;
    int n = in_sizes[0] / 9;            // number of matrices
    int nFullTiles = n / MATS;

    int grid = 148 * 8;                  // one full wave: 8 CTAs/SM
    int maxUseful = nFullTiles > 0 ? nFullTiles : 1;
    if (grid > maxUseful) grid = maxUseful;

    mat2twist_kernel<<<grid, TPB>>>(in, out, n, nFullTiles);
}

// round 12
// speedup vs baseline: 1.1097x; 1.1097x over previous
#include <cuda_runtime.h>
#include <cuda_pipeline.h>

// Mat2Twist: rotation matrix (3x3) -> axis-angle (3). Memory-bound.
//
// R12: flat (non-persistent) launch + one double-buffered cp.async overlap.
//   Each CTA handles exactly 2 tiles of 256 matrices:
//     prefetch(t0), prefetch(t1), wait t0 -> compute+store t0 (t1 loads in
//     flight), wait t1 -> compute+store t1.
//   - R7 tile geometry per stage (best flat-launch DRAM%), 2.25 f4/thread
//   - cp.async keeps loads out of the register/L1 path (R8's win) while the
//     flat launch avoids the persistent-grid bench penalty (R8/R11's loss)
//   - __stcs streaming stores. smem 24.6KB -> 8 CTAs/SM.

#define TPB   256
#define MATS  256
#define F4T   ((MATS * 9) / 4)   // 576 float4 per tile
#define MPB   (2 * MATS)         // 512 matrices per CTA

__device__ __forceinline__ void prefetch_tile(
    const float4* __restrict__ gin4, int tile, float4* dst, int tid)
{
    const float4* src = gin4 + (size_t)tile * F4T;
    __pipeline_memcpy_async(dst + tid,       src + tid,       16);
    __pipeline_memcpy_async(dst + tid + TPB, src + tid + TPB, 16);
    if (tid < F4T - 2 * TPB)
        __pipeline_memcpy_async(dst + tid + 2 * TPB, src + tid + 2 * TPB, 16);
}

__device__ __forceinline__ void compute_store_tile(
    const float4* sbuf, float* s_out, float* __restrict__ out,
    int tile, int tid)
{
    const float* m = reinterpret_cast<const float*>(sbuf) + tid * 9;
    float m00 = m[0], m01 = m[1], m02 = m[2];
    float m10 = m[3], m11 = m[4], m12 = m[5];
    float m20 = m[6], m21 = m[7], m22 = m[8];

    float c = 0.5f * (m00 + m11 + m22 - 1.0f);
    c = fminf(1.0f, fmaxf(-1.0f, c));
    // sin(acos(c)) = sqrt(1-c^2); theta in [0.1, pi-0.1] keeps this safe
    float scale = 0.5f * acosf(c) * rsqrtf(fmaxf(1.0f - c * c, 1e-12f));

    s_out[tid * 3 + 0] = scale * (m21 - m12);
    s_out[tid * 3 + 1] = scale * (m02 - m20);
    s_out[tid * 3 + 2] = scale * (m10 - m01);
    __syncthreads();

    float4* __restrict__ gout =
        reinterpret_cast<float4*>(out + (size_t)tile * MATS * 3);
    const float4* so4 = reinterpret_cast<const float4*>(s_out);
    if (tid < (MATS * 3) / 4)
        __stcs(gout + tid, so4[tid]);
}

__global__ __launch_bounds__(TPB) void mat2twist_kernel(
    const float* __restrict__ in, float* __restrict__ out,
    int n, int nFullTiles)
{
    __shared__ float4 s_in[2][F4T];          // 2 * 9216 B
    __shared__ float  s_out[2][MATS * 3];    // 2 * 3072 B

    const int tid = threadIdx.x;
    const float4* __restrict__ gin4 = reinterpret_cast<const float4*>(in);

    const int t0 = blockIdx.x * 2;
    const int t1 = t0 + 1;

    // ---- prefetch both tiles, one commit group each ----
    if (t0 < nFullTiles) prefetch_tile(gin4, t0, s_in[0], tid);
    __pipeline_commit();
    if (t1 < nFullTiles) prefetch_tile(gin4, t1, s_in[1], tid);
    __pipeline_commit();

    // ---- tile 0: compute+store while tile 1's loads are in flight ----
    if (t0 < nFullTiles) {
        __pipeline_wait_prior(1);
        __syncthreads();
        compute_store_tile(s_in[0], s_out[0], out, t0, tid);
    }

    // ---- tile 1 ----
    if (t1 < nFullTiles) {
        __pipeline_wait_prior(0);
        __syncthreads();
        compute_store_tile(s_in[1], s_out[1], out, t1, tid);
    }

    // ---- tail: matrices beyond the last full tile (scalar) ----
    int tailStart = nFullTiles * MATS;
    for (int i = tailStart + blockIdx.x * TPB + tid; i < n;
         i += gridDim.x * TPB) {
        const float* m = in + (size_t)i * 9;
        float m00 = m[0], m01 = m[1], m02 = m[2];
        float m10 = m[3], m11 = m[4], m12 = m[5];
        float m20 = m[6], m21 = m[7], m22 = m[8];

        float c = 0.5f * (m00 + m11 + m22 - 1.0f);
        c = fminf(1.0f, fmaxf(-1.0f, c));
        float scale = 0.5f * acosf(c) * rsqrtf(fmaxf(1.0f - c * c, 1e-12f));

        out[(size_t)i * 3 + 0] = scale * (m21 - m12);
        out[(size_t)i * 3 + 1] = scale * (m02 - m20);
        out[(size_t)i * 3 + 2] = scale * (m10 - m01);
    }
}

extern "C" void kernel_launch(void* const* d_in, const int* in_sizes, int n_in,
                              void* d_out, int out_size)
{
    const float* in = (const float*)d_in[0];
    float* out = (float*)d_out;
    int n = in_sizes[0] / 9;            // number of matrices
    int nFullTiles = n / MATS;

    int grid = (n + MPB - 1) / MPB;     // 2 tiles per CTA, non-persistent
    if (grid < 1) grid = 1;

    mat2twist_kernel<<<grid, TPB>>>(in, out, n, nFullTiles);
}